// round 12
// baseline (speedup 1.0000x reference)
#include <cuda_runtime.h>
#include <cuda_fp16.h>
#include <cstdint>

// ===================== problem constants =====================
#define NNF 128
#define NEF 64
#define NGF 64
#define HID 128
#define TGT 64

#define THREADS 448
#define NWARPS  14
#define GRID_X  152

#define KT1 24   // 384/16 k-tiles, GEMM1
#define NT1 16   // 128/8  n-tiles, GEMM1 (8 per phase)
#define KT2 8    // 128/16 k-tiles, GEMM2

// ===================== smem offsets (bytes) =====================
#define S_W1  0u        // 24 kt x 8 pairs x 32 lanes x 16B = 98304
#define S_W2  98304u    // 8 kt x 4 pairs x 32 x 16B = 16384
#define S_B1  114688u   // 512
#define S_B2  115200u   // 256
#define S_H   115456u   // 14 warps x 8192 (h for both phases)
#define S_TOTAL (S_H + NWARPS * 8192u)   // 230144  (< 232448 cap)

// ===================== helpers =====================
__device__ __forceinline__ uint32_t pack2h(float lo, float hi) {
    uint32_t r;
    asm("cvt.rn.f16x2.f32 %0, %1, %2;" : "=r"(r) : "f"(hi), "f"(lo));
    return r;
}
// D += A * B  (m16n8k16, fp16 in, f32 accum)
__device__ __forceinline__ void mma_f16(float* c, const uint32_t* a, uint32_t b0, uint32_t b1) {
    asm volatile("mma.sync.aligned.m16n8k16.row.col.f32.f16.f16.f32 "
        "{%0,%1,%2,%3}, {%4,%5,%6,%7}, {%8,%9}, {%0,%1,%2,%3};"
        : "+f"(c[0]), "+f"(c[1]), "+f"(c[2]), "+f"(c[3])
        : "r"(a[0]), "r"(a[1]), "r"(a[2]), "r"(a[3]), "r"(b0), "r"(b1));
}
__device__ __forceinline__ void load8(float2* v, const float* p0, const float* p1,
                                      const float* p2, const float* p3) {
    v[0] = *(const float2*)p0; v[1] = *(const float2*)(p0 + 8);
    v[2] = *(const float2*)p1; v[3] = *(const float2*)(p1 + 8);
    v[4] = *(const float2*)p2; v[5] = *(const float2*)(p2 + 8);
    v[6] = *(const float2*)p3; v[7] = *(const float2*)(p3 + 8);
}
__device__ __forceinline__ void cvt8(uint32_t* af, const float2* v) {
    af[0] = pack2h(v[0].x, v[0].y);  // (r00, c0)
    af[1] = pack2h(v[2].x, v[2].y);  // (r01, c0)
    af[2] = pack2h(v[1].x, v[1].y);  // (r00, c0+8)
    af[3] = pack2h(v[3].x, v[3].y);  // (r01, c0+8)
    af[4] = pack2h(v[4].x, v[4].y);  // (r10, c0)
    af[5] = pack2h(v[6].x, v[6].y);  // (r11, c0)
    af[6] = pack2h(v[5].x, v[5].y);  // (r10, c0+8)
    af[7] = pack2h(v[7].x, v[7].y);  // (r11, c0+8)
}

// ===================== device scratch (pair-interleaved fragments) =====================
__device__ __align__(16) uint2 g_w1[KT1 * NT1 * 32];
__device__ __align__(16) uint2 g_w2[KT2 * 8 * 32];
__device__ unsigned int g_counter;

// W1 [384,128], W2 [128,64] ([k][n] row-major) -> per-lane m16n8k16 B fragments,
// paired: uint4 entry ((kt*8+np)*32+lane) = {frag(nt=2np), frag(nt=2np+1)}.
// frag(kt,nt,lane) = { {W[k0][n],W[k0+1][n]}, {W[k0+8][n],W[k0+9][n]} },
// k0 = kt*16+(lane&3)*2, n = nt*8+(lane>>2).
__global__ void prep_kernel(const float* __restrict__ W1, const float* __restrict__ W2) {
    int idx = blockIdx.x * blockDim.x + threadIdx.x;
    if (idx == 0) g_counter = 0u;
    const int total1 = KT1 * NT1 * 32;
    if (idx < total1) {
        int lane = idx & 31, tile = idx >> 5;
        int nt = tile % NT1, kt = tile / NT1;
        int k0 = kt * 16 + (lane & 3) * 2;
        int n  = nt * 8 + (lane >> 2);
        float w00 = W1[(size_t)k0 * HID + n];
        float w01 = W1[(size_t)(k0 + 1) * HID + n];
        float w10 = W1[(size_t)(k0 + 8) * HID + n];
        float w11 = W1[(size_t)(k0 + 9) * HID + n];
        size_t dst = (size_t)2 * (((size_t)kt * 8 + (nt >> 1)) * 32 + lane) + (nt & 1);
        g_w1[dst] = make_uint2(pack2h(w00, w01), pack2h(w10, w11));
    } else if (idx < total1 + KT2 * 8 * 32) {
        int j = idx - total1;
        int lane = j & 31, tile = j >> 5;
        int nt = tile % 8, kt = tile / 8;
        int k0 = kt * 16 + (lane & 3) * 2;
        int n  = nt * 8 + (lane >> 2);
        float w00 = W2[(size_t)k0 * TGT + n];
        float w01 = W2[(size_t)(k0 + 1) * TGT + n];
        float w10 = W2[(size_t)(k0 + 8) * TGT + n];
        float w11 = W2[(size_t)(k0 + 9) * TGT + n];
        size_t dst = (size_t)2 * (((size_t)kt * 4 + (nt >> 1)) * 32 + lane) + (nt & 1);
        g_w2[dst] = make_uint2(pack2h(w00, w01), pack2h(w10, w11));
    }
}

// ===================== main fused kernel =====================
extern "C" __global__ void __launch_bounds__(THREADS, 1)
edge_mlp(const float* __restrict__ ek, const float* __restrict__ vrk,
         const float* __restrict__ vsk, const float* __restrict__ u,
         const int* __restrict__ batch,
         const float* __restrict__ b1, const float* __restrict__ b2,
         float* __restrict__ out, int ngroups) {
    extern __shared__ __align__(16) unsigned char smem[];
    const int tid = threadIdx.x;

    // -------- prologue: weight fragments + biases to smem --------
    {
        uint4* d = (uint4*)(smem + S_W1);
        const uint4* s = (const uint4*)g_w1;
        for (int i = tid; i < 98304 / 16; i += THREADS) d[i] = s[i];
        d = (uint4*)(smem + S_W2); s = (const uint4*)g_w2;
        for (int i = tid; i < 16384 / 16; i += THREADS) d[i] = s[i];
        float* b1s = (float*)(smem + S_B1);
        float* b2s = (float*)(smem + S_B2);
        if (tid < HID) b1s[tid] = b1[tid];
        if (tid < TGT) b2s[tid] = b2[tid];
    }
    __syncthreads();

    const uint4* w1p = (const uint4*)(smem + S_W1);
    const uint4* w2p = (const uint4*)(smem + S_W2);
    const float* b1s = (const float*)(smem + S_B1);
    const float* b2s = (const float*)(smem + S_B2);

    const int lane = tid & 31;
    const int wid  = tid >> 5;
    const int qrow = lane >> 2;        // 0..7
    const int qcol = (lane & 3) * 2;   // 0,2,4,6

    uint4* hbuf = (uint4*)(smem + S_H + (size_t)wid * 8192u);

    unsigned int cur = 0xFFFFFFFFu;
    if (lane == 0) cur = atomicAdd(&g_counter, 1u);
    cur = __shfl_sync(0xFFFFFFFFu, cur, 0);

    while (cur < (unsigned)ngroups) {
        unsigned int nxt = 0xFFFFFFFFu;
        if (lane == 0) nxt = atomicAdd(&g_counter, 1u);

        const int rbase = (int)cur * 32;
        const int r00 = rbase + qrow,      r01 = r00 + 8;
        const int r10 = rbase + 16 + qrow, r11 = r10 + 8;
        const int g00 = batch[r00], g01 = batch[r01];
        const int g10 = batch[r10], g11 = batch[r11];

        // ============ GEMM1 in two N-phases (hidden cols ph*64..ph*64+63) ============
        #pragma unroll 1
        for (int ph = 0; ph < 2; ++ph) {
            const int ph4 = ph * 4;
            float acc[64];   // [rb(2)][ntlocal(8)][4]
            #pragma unroll
            for (int i = 0; i < 64; ++i) acc[i] = 0.f;

            // distance-2 x prefetch: vA holds kt, vB holds kt+1
            float2 vA[8], vB[8];
            uint32_t af[8];
            const float *p0 = ek + (size_t)r00 * NEF + qcol;
            const float *p1 = ek + (size_t)r01 * NEF + qcol;
            const float *p2 = ek + (size_t)r10 * NEF + qcol;
            const float *p3 = ek + (size_t)r11 * NEF + qcol;
            load8(vA, p0, p1, p2, p3);          // kt = 0
            p0 += 16; p1 += 16; p2 += 16; p3 += 16;
            load8(vB, p0, p1, p2, p3);          // kt = 1

            // advance pointers to kt+2's location and load; kt: current tile
            #pragma unroll 1
            for (int kt = 0; kt < KT1; ++kt) {
                cvt8(af, vA);                   // consume kt (loaded 2 bodies ago)
                #pragma unroll
                for (int i = 0; i < 8; ++i) vA[i] = vB[i];   // shift pipeline
                if (kt < KT1 - 2) {
                    const int kn = kt + 2;
                    if (kn == 4) {
                        p0 = vrk + (size_t)r00 * NNF + qcol;
                        p1 = vrk + (size_t)r01 * NNF + qcol;
                        p2 = vrk + (size_t)r10 * NNF + qcol;
                        p3 = vrk + (size_t)r11 * NNF + qcol;
                    } else if (kn == 12) {
                        p0 = vsk + (size_t)r00 * NNF + qcol;
                        p1 = vsk + (size_t)r01 * NNF + qcol;
                        p2 = vsk + (size_t)r10 * NNF + qcol;
                        p3 = vsk + (size_t)r11 * NNF + qcol;
                    } else if (kn == 20) {
                        p0 = u + (size_t)g00 * NGF + qcol;
                        p1 = u + (size_t)g01 * NGF + qcol;
                        p2 = u + (size_t)g10 * NGF + qcol;
                        p3 = u + (size_t)g11 * NGF + qcol;
                    } else {
                        p0 += 16; p1 += 16; p2 += 16; p3 += 16;
                    }
                    load8(vB, p0, p1, p2, p3);
                }
                const uint4* bw = w1p + ((size_t)kt * 8 + ph4) * 32 + lane;
                #pragma unroll
                for (int np = 0; np < 4; ++np) {
                    const uint4 f = bw[np * 32];
                    mma_f16(acc + (np * 2) * 4,          af,     f.x, f.y);
                    mma_f16(acc + 32 + (np * 2) * 4,     af + 4, f.x, f.y);
                    mma_f16(acc + (np * 2 + 1) * 4,      af,     f.z, f.w);
                    mma_f16(acc + 32 + (np * 2 + 1) * 4, af + 4, f.z, f.w);
                }
            }

            // ---- bias + ReLU ----
            #pragma unroll
            for (int nt = 0; nt < 8; ++nt) {
                const float2 bb = *(const float2*)(b1s + ph * 64 + nt * 8 + qcol);
                #pragma unroll
                for (int rb = 0; rb < 2; ++rb) {
                    float* a = acc + rb * 32 + nt * 4;
                    a[0] = fmaxf(a[0] + bb.x, 0.f);
                    a[1] = fmaxf(a[1] + bb.y, 0.f);
                    a[2] = fmaxf(a[2] + bb.x, 0.f);
                    a[3] = fmaxf(a[3] + bb.y, 0.f);
                }
            }
            // ---- pack + spill h to per-warp smem (A-frag layout for GEMM2) ----
            #pragma unroll
            for (int j = 0; j < 4; ++j) {
                const int kk = ph4 + j;
                #pragma unroll
                for (int rb = 0; rb < 2; ++rb) {
                    const float* s = acc + rb * 32 + j * 8;
                    uint4 q;
                    q.x = pack2h(s[0], s[1]);
                    q.y = pack2h(s[2], s[3]);
                    q.z = pack2h(s[4], s[5]);
                    q.w = pack2h(s[6], s[7]);
                    hbuf[(kk * 2 + rb) * 32 + lane] = q;
                }
            }
        }

        // ================= GEMM2: h (smem) @ W2 =================
        float c2[64];
        #pragma unroll
        for (int i = 0; i < 64; ++i) c2[i] = 0.f;

        #pragma unroll 1
        for (int kk = 0; kk < KT2; ++kk) {
            uint4 A0 = hbuf[(kk * 2 + 0) * 32 + lane];
            uint4 A1 = hbuf[(kk * 2 + 1) * 32 + lane];
            const uint32_t* a0 = (const uint32_t*)&A0;
            const uint32_t* a1 = (const uint32_t*)&A1;
            const uint4* bw = w2p + (size_t)kk * 4 * 32 + lane;
            #pragma unroll
            for (int np = 0; np < 4; ++np) {
                const uint4 f = bw[np * 32];
                mma_f16(c2 + (np * 2) * 4,          a0, f.x, f.y);
                mma_f16(c2 + 32 + (np * 2) * 4,     a1, f.x, f.y);
                mma_f16(c2 + (np * 2 + 1) * 4,      a0, f.z, f.w);
                mma_f16(c2 + 32 + (np * 2 + 1) * 4, a1, f.z, f.w);
            }
        }

        // ================= epilogue: + b2, store fp32 =================
        #pragma unroll
        for (int nt = 0; nt < 8; ++nt) {
            const float2 bb = *(const float2*)(b2s + nt * 8 + qcol);
            {
                const float* c = c2 + nt * 4;
                float2 o0, o1;
                o0.x = c[0] + bb.x; o0.y = c[1] + bb.y;
                o1.x = c[2] + bb.x; o1.y = c[3] + bb.y;
                *(float2*)(out + (size_t)r00 * TGT + nt * 8 + qcol) = o0;
                *(float2*)(out + (size_t)r01 * TGT + nt * 8 + qcol) = o1;
            }
            {
                const float* c = c2 + 32 + nt * 4;
                float2 o0, o1;
                o0.x = c[0] + bb.x; o0.y = c[1] + bb.y;
                o1.x = c[2] + bb.x; o1.y = c[3] + bb.y;
                *(float2*)(out + (size_t)r10 * TGT + nt * 8 + qcol) = o0;
                *(float2*)(out + (size_t)r11 * TGT + nt * 8 + qcol) = o1;
            }
        }

        cur = __shfl_sync(0xFFFFFFFFu, nxt, 0);
    }
}

// ===================== launch =====================
extern "C" void kernel_launch(void* const* d_in, const int* in_sizes, int n_in,
                              void* d_out, int out_size) {
    (void)n_in; (void)out_size;
    const float* ek  = (const float*)d_in[0];
    const float* vrk = (const float*)d_in[1];
    const float* vsk = (const float*)d_in[2];
    const float* u   = (const float*)d_in[3];
    const int*   batch = (const int*)d_in[4];
    const float* W1  = (const float*)d_in[5];
    const float* b1  = (const float*)d_in[6];
    const float* W2  = (const float*)d_in[7];
    const float* b2  = (const float*)d_in[8];
    float* out = (float*)d_out;

    const int E = in_sizes[0] / NEF;
    const int ngroups = E / 32;

    const int prep_total = KT1 * NT1 * 32 + KT2 * 8 * 32;
    prep_kernel<<<(prep_total + 255) / 256, 256>>>(W1, W2);

    cudaFuncSetAttribute(edge_mlp, cudaFuncAttributeMaxDynamicSharedMemorySize, S_TOTAL);
    edge_mlp<<<GRID_X, THREADS, S_TOTAL>>>(ek, vrk, vsk, u, batch, b1, b2, out, ngroups);
}

// round 13
// speedup vs baseline: 1.9872x; 1.9872x over previous
#include <cuda_runtime.h>
#include <cuda_fp16.h>
#include <cstdint>

// ===================== problem constants =====================
#define NNF 128
#define NEF 64
#define NGF 64
#define HID 128
#define TGT 64

#define THREADS 512
#define WARPS 16
#define GRID_X 152

// fragment tile counts
#define KT1 24   // 384/16 k-tiles, GEMM1
#define NT1 16   // 128/8  n-tiles, GEMM1
#define KT2 8    // 128/16 k-tiles, GEMM2
#define NT2 8    // 64/8   n-tiles, GEMM2

// ===================== smem offsets (bytes) =====================
#define S_W1  0u        // 24 kt x 8 pairs x 32 lanes x 16B = 98304
#define S_W2  98304u    // 8 kt x 4 pairs x 32 x 16B = 16384
#define S_B1  114688u   // 512
#define S_B2  115200u   // 256
#define S_TOTAL 115456u

// ===================== helpers =====================
__device__ __forceinline__ uint32_t pack2h(float lo, float hi) {
    // f16x2 with 'lo' in low 16 bits (first PTX source -> high half)
    uint32_t r;
    asm("cvt.rn.f16x2.f32 %0, %1, %2;" : "=r"(r) : "f"(hi), "f"(lo));
    return r;
}
// D += A * B  (m16n8k16, fp16 in, f32 accum)
__device__ __forceinline__ void mma_f16(float* c, const uint32_t* a, uint32_t b0, uint32_t b1) {
    asm volatile("mma.sync.aligned.m16n8k16.row.col.f32.f16.f16.f32 "
        "{%0,%1,%2,%3}, {%4,%5,%6,%7}, {%8,%9}, {%0,%1,%2,%3};"
        : "+f"(c[0]), "+f"(c[1]), "+f"(c[2]), "+f"(c[3])
        : "r"(a[0]), "r"(a[1]), "r"(a[2]), "r"(a[3]), "r"(b0), "r"(b1));
}

// ===================== device scratch (pair-interleaved fragments) =====================
__device__ __align__(16) uint2 g_w1[KT1 * NT1 * 32];
__device__ __align__(16) uint2 g_w2[KT2 * NT2 * 32];
__device__ unsigned int g_counter;

// W1 [384,128] and W2 [128,64] ([k][n] row-major) -> per-lane m16n8k16 B
// fragments (fp16), PAIRED: uint4 entry ((kt*NP+np)*32+lane) holds
// {frag(nt=2np), frag(nt=2np+1)} where
// frag(kt,nt,lane) = { {W[k0][n],W[k0+1][n]}, {W[k0+8][n],W[k0+9][n]} },
// k0 = kt*16+(lane&3)*2, n = nt*8+(lane>>2).
__global__ void prep_kernel(const float* __restrict__ W1, const float* __restrict__ W2) {
    int idx = blockIdx.x * blockDim.x + threadIdx.x;
    if (idx == 0) g_counter = 0u;
    const int total1 = KT1 * NT1 * 32;
    if (idx < total1) {
        int lane = idx & 31, tile = idx >> 5;
        int nt = tile % NT1, kt = tile / NT1;
        int k0 = kt * 16 + (lane & 3) * 2;
        int n  = nt * 8 + (lane >> 2);
        float w00 = W1[(size_t)k0 * HID + n];
        float w01 = W1[(size_t)(k0 + 1) * HID + n];
        float w10 = W1[(size_t)(k0 + 8) * HID + n];
        float w11 = W1[(size_t)(k0 + 9) * HID + n];
        size_t dst = (size_t)2 * (((size_t)kt * 8 + (nt >> 1)) * 32 + lane) + (nt & 1);
        g_w1[dst] = make_uint2(pack2h(w00, w01), pack2h(w10, w11));
    } else if (idx < total1 + KT2 * NT2 * 32) {
        int j = idx - total1;
        int lane = j & 31, tile = j >> 5;
        int nt = tile % NT2, kt = tile / NT2;
        int k0 = kt * 16 + (lane & 3) * 2;
        int n  = nt * 8 + (lane >> 2);
        float w00 = W2[(size_t)k0 * TGT + n];
        float w01 = W2[(size_t)(k0 + 1) * TGT + n];
        float w10 = W2[(size_t)(k0 + 8) * TGT + n];
        float w11 = W2[(size_t)(k0 + 9) * TGT + n];
        size_t dst = (size_t)2 * (((size_t)kt * 4 + (nt >> 1)) * 32 + lane) + (nt & 1);
        g_w2[dst] = make_uint2(pack2h(w00, w01), pack2h(w10, w11));
    }
}

// ===================== main fused kernel =====================
extern "C" __global__ void __launch_bounds__(THREADS, 1)
edge_mlp(const float* __restrict__ ek, const float* __restrict__ vrk,
         const float* __restrict__ vsk, const float* __restrict__ u,
         const int* __restrict__ batch,
         const float* __restrict__ b1, const float* __restrict__ b2,
         float* __restrict__ out, int ngroups) {
    extern __shared__ __align__(16) unsigned char smem[];
    const int tid = threadIdx.x;

    // -------- prologue: weight fragments + biases to smem --------
    {
        uint4* d = (uint4*)(smem + S_W1);
        const uint4* s = (const uint4*)g_w1;
        for (int i = tid; i < 98304 / 16; i += THREADS) d[i] = s[i];
        d = (uint4*)(smem + S_W2); s = (const uint4*)g_w2;
        for (int i = tid; i < 16384 / 16; i += THREADS) d[i] = s[i];
        float* b1s = (float*)(smem + S_B1);
        float* b2s = (float*)(smem + S_B2);
        if (tid < HID) b1s[tid] = b1[tid];
        if (tid < TGT) b2s[tid] = b2[tid];
    }
    __syncthreads();

    const uint4* w1p = (const uint4*)(smem + S_W1);
    const uint4* w2p = (const uint4*)(smem + S_W2);
    const float* b1s = (const float*)(smem + S_B1);
    const float* b2s = (const float*)(smem + S_B2);

    const int lane = tid & 31;
    const int qrow = lane >> 2;        // 0..7
    const int qcol = (lane & 3) * 2;   // 0,2,4,6

    // dynamic work stealing (group = 16 edge rows)
    unsigned int cur = 0xFFFFFFFFu;
    if (lane == 0) cur = atomicAdd(&g_counter, 1u);
    cur = __shfl_sync(0xFFFFFFFFu, cur, 0);

    while (cur < (unsigned)ngroups) {
        unsigned int nxt = 0xFFFFFFFFu;
        if (lane == 0) nxt = atomicAdd(&g_counter, 1u);   // issued early, latency hidden

        const int r0 = (int)cur * 16 + qrow;
        const int r1 = r0 + 8;
        const int gb0 = batch[r0];
        const int gb1 = batch[r1];

        float acc[64];   // GEMM1 C: 16 n-tiles x 4
        #pragma unroll
        for (int i = 0; i < 64; ++i) acc[i] = 0.f;

        // ================= GEMM1: K = 384 in 24 k16-tiles, pipelined loads =================
        float2 v0, v1, v2, v3;
        {
            const float* p0 = ek + (size_t)r0 * NEF + qcol;
            const float* p1 = ek + (size_t)r1 * NEF + qcol;
            v0 = *(const float2*)p0;       v1 = *(const float2*)p1;
            v2 = *(const float2*)(p0 + 8); v3 = *(const float2*)(p1 + 8);
        }
        #pragma unroll 1
        for (int kt = 0; kt < KT1; ++kt) {
            // ---- prefetch kt+1 ----
            float2 n0, n1, n2, n3;
            {
                const int kn = (kt + 1 < KT1) ? kt + 1 : KT1 - 1;
                const int c0 = kn * 16 + qcol;
                const float *p0, *p1;
                if (kn < 4)       { p0 = ek  + (size_t)r0 * NEF + c0;          p1 = ek  + (size_t)r1 * NEF + c0; }
                else if (kn < 12) { p0 = vrk + (size_t)r0 * NNF + (c0 - 64);   p1 = vrk + (size_t)r1 * NNF + (c0 - 64); }
                else if (kn < 20) { p0 = vsk + (size_t)r0 * NNF + (c0 - 192);  p1 = vsk + (size_t)r1 * NNF + (c0 - 192); }
                else              { p0 = u + (size_t)gb0 * NGF + (c0 - 320);   p1 = u + (size_t)gb1 * NGF + (c0 - 320); }
                n0 = *(const float2*)p0;       n1 = *(const float2*)p1;
                n2 = *(const float2*)(p0 + 8); n3 = *(const float2*)(p1 + 8);
            }

            // ---- A fragment: single fp16 ----
            uint32_t a[4];
            a[0] = pack2h(v0.x, v0.y);
            a[1] = pack2h(v1.x, v1.y);
            a[2] = pack2h(v2.x, v2.y);
            a[3] = pack2h(v3.x, v3.y);

            const uint4* bw = w1p + (size_t)kt * 8 * 32 + lane;
            #pragma unroll
            for (int np = 0; np < 8; ++np) {
                const uint4 f = bw[np * 32];        // two n-tile fragments per LDS.128
                mma_f16(acc + (np * 2) * 4,     a, f.x, f.y);
                mma_f16(acc + (np * 2 + 1) * 4, a, f.z, f.w);
            }

            v0 = n0; v1 = n1; v2 = n2; v3 = n3;
        }

        // ================= bias + ReLU =================
        #pragma unroll
        for (int nt = 0; nt < NT1; ++nt) {
            const float2 bb = *(const float2*)(b1s + nt * 8 + qcol);
            acc[nt * 4 + 0] = fmaxf(acc[nt * 4 + 0] + bb.x, 0.f);
            acc[nt * 4 + 1] = fmaxf(acc[nt * 4 + 1] + bb.y, 0.f);
            acc[nt * 4 + 2] = fmaxf(acc[nt * 4 + 2] + bb.x, 0.f);
            acc[nt * 4 + 3] = fmaxf(acc[nt * 4 + 3] + bb.y, 0.f);
        }

        // ================= GEMM2: h [16x128] @ W2 [128x64], register A =================
        float c2[32];
        #pragma unroll
        for (int i = 0; i < 32; ++i) c2[i] = 0.f;

        #pragma unroll
        for (int kt = 0; kt < KT2; ++kt) {
            // C1 fragment (n-tiles 2kt,2kt+1) == A2 fragment for k-cols 16kt..16kt+15
            const float* s0 = acc + kt * 8;
            uint32_t a[4];
            a[0] = pack2h(s0[0], s0[1]); a[1] = pack2h(s0[2], s0[3]);
            a[2] = pack2h(s0[4], s0[5]); a[3] = pack2h(s0[6], s0[7]);

            const uint4* bw = w2p + (size_t)kt * 4 * 32 + lane;
            #pragma unroll
            for (int np = 0; np < 4; ++np) {
                const uint4 f = bw[np * 32];
                mma_f16(c2 + (np * 2) * 4,     a, f.x, f.y);
                mma_f16(c2 + (np * 2 + 1) * 4, a, f.z, f.w);
            }
        }

        // ================= epilogue: + b2, store fp32 =================
        #pragma unroll
        for (int nt = 0; nt < NT2; ++nt) {
            const float2 bb = *(const float2*)(b2s + nt * 8 + qcol);
            float2 o0, o1;
            o0.x = c2[nt * 4 + 0] + bb.x;
            o0.y = c2[nt * 4 + 1] + bb.y;
            o1.x = c2[nt * 4 + 2] + bb.x;
            o1.y = c2[nt * 4 + 3] + bb.y;
            *(float2*)(out + (size_t)r0 * TGT + nt * 8 + qcol) = o0;
            *(float2*)(out + (size_t)r1 * TGT + nt * 8 + qcol) = o1;
        }

        cur = __shfl_sync(0xFFFFFFFFu, nxt, 0);
    }
}

// ===================== launch =====================
extern "C" void kernel_launch(void* const* d_in, const int* in_sizes, int n_in,
                              void* d_out, int out_size) {
    (void)n_in; (void)out_size;
    const float* ek  = (const float*)d_in[0];
    const float* vrk = (const float*)d_in[1];
    const float* vsk = (const float*)d_in[2];
    const float* u   = (const float*)d_in[3];
    const int*   batch = (const int*)d_in[4];
    const float* W1  = (const float*)d_in[5];
    const float* b1  = (const float*)d_in[6];
    const float* W2  = (const float*)d_in[7];
    const float* b2  = (const float*)d_in[8];
    float* out = (float*)d_out;

    const int E = in_sizes[0] / NEF;
    const int ngroups = E / 16;

    const int prep_total = KT1 * NT1 * 32 + KT2 * NT2 * 32;
    prep_kernel<<<(prep_total + 255) / 256, 256>>>(W1, W2);

    cudaFuncSetAttribute(edge_mlp, cudaFuncAttributeMaxDynamicSharedMemorySize, S_TOTAL);
    edge_mlp<<<GRID_X, THREADS, S_TOTAL>>>(ek, vrk, vsk, u, batch, b1, b2, out, ngroups);
}

// round 14
// speedup vs baseline: 2.1035x; 1.0585x over previous
#include <cuda_runtime.h>
#include <cuda_fp16.h>
#include <cstdint>

// ===================== problem constants =====================
#define NNF 128
#define NEF 64
#define NGF 64
#define HID 128
#define TGT 64

#define THREADS 512
#define WARPS 16
#define GRID_X 152

// fragment tile counts
#define KT1 24   // 384/16 k-tiles, GEMM1
#define NT1 16   // 128/8  n-tiles, GEMM1
#define KT2 8    // 128/16 k-tiles, GEMM2
#define NT2 8    // 64/8   n-tiles, GEMM2

// ===================== smem offsets (bytes) =====================
#define S_W1  0u        // 24 kt x 8 pairs x 32 lanes x 16B = 98304
#define S_W2  98304u    // 8 kt x 4 pairs x 32 x 16B = 16384
#define S_B1  114688u   // 512
#define S_B2  115200u   // 256
#define S_TOTAL 115456u

// ===================== helpers =====================
__device__ __forceinline__ uint32_t pack2h(float lo, float hi) {
    // f16x2 with 'lo' in low 16 bits (first PTX source -> high half)
    uint32_t r;
    asm("cvt.rn.f16x2.f32 %0, %1, %2;" : "=r"(r) : "f"(hi), "f"(lo));
    return r;
}
// D += A * B  (m16n8k16, fp16 in, f32 accum)
__device__ __forceinline__ void mma_f16(float* c, const uint32_t* a, uint32_t b0, uint32_t b1) {
    asm volatile("mma.sync.aligned.m16n8k16.row.col.f32.f16.f16.f32 "
        "{%0,%1,%2,%3}, {%4,%5,%6,%7}, {%8,%9}, {%0,%1,%2,%3};"
        : "+f"(c[0]), "+f"(c[1]), "+f"(c[2]), "+f"(c[3])
        : "r"(a[0]), "r"(a[1]), "r"(a[2]), "r"(a[3]), "r"(b0), "r"(b1));
}

// ===================== device scratch (pair-interleaved fragments) =====================
__device__ __align__(16) uint2 g_w1[KT1 * NT1 * 32];
__device__ __align__(16) uint2 g_w2[KT2 * NT2 * 32];
__device__ unsigned int g_counter;

// W1 [384,128] ([k][n] row-major) -> per-lane m16n8k16 B fragments (fp16), with a
// K-PERMUTATION inside each 16-k tile: logical k {2q,2q+1,2q+8,2q+9} <- memory
// cols {4q,4q+1,4q+2,4q+3} (q = lane&3). So for W1:
//   b0 = {W[k0][n], W[k0+1][n]},  b1 = {W[k0+2][n], W[k0+3][n]},  k0 = kt*16 + 4q.
// The A side loads one contiguous float4 per lane (cols 4q..4q+3) and maps
// .xy -> a0/a1 (logical 2q,2q+1), .zw -> a2/a3 (logical 2q+8,2q+9). The same
// permutation on both operands leaves the k-sum invariant.
// W2 [128,64] keeps the STANDARD layout (its A operand comes from registers in
// logical order via the C1->A2 fragment identity):
//   b0 = {W[k0][n], W[k0+1][n]}, b1 = {W[k0+8][n], W[k0+9][n]}, k0 = kt*16 + 2q.
// PAIRED storage: uint4 entry ((kt*NP+np)*32+lane) = {frag(nt=2np), frag(nt=2np+1)}.
__global__ void prep_kernel(const float* __restrict__ W1, const float* __restrict__ W2) {
    int idx = blockIdx.x * blockDim.x + threadIdx.x;
    if (idx == 0) g_counter = 0u;
    const int total1 = KT1 * NT1 * 32;
    if (idx < total1) {
        int lane = idx & 31, tile = idx >> 5;
        int nt = tile % NT1, kt = tile / NT1;
        int k0 = kt * 16 + (lane & 3) * 4;        // permuted: 4 consecutive rows
        int n  = nt * 8 + (lane >> 2);
        float w00 = W1[(size_t)k0 * HID + n];
        float w01 = W1[(size_t)(k0 + 1) * HID + n];
        float w10 = W1[(size_t)(k0 + 2) * HID + n];
        float w11 = W1[(size_t)(k0 + 3) * HID + n];
        size_t dst = (size_t)2 * (((size_t)kt * 8 + (nt >> 1)) * 32 + lane) + (nt & 1);
        g_w1[dst] = make_uint2(pack2h(w00, w01), pack2h(w10, w11));
    } else if (idx < total1 + KT2 * NT2 * 32) {
        int j = idx - total1;
        int lane = j & 31, tile = j >> 5;
        int nt = tile % NT2, kt = tile / NT2;
        int k0 = kt * 16 + (lane & 3) * 2;        // standard layout for W2
        int n  = nt * 8 + (lane >> 2);
        float w00 = W2[(size_t)k0 * TGT + n];
        float w01 = W2[(size_t)(k0 + 1) * TGT + n];
        float w10 = W2[(size_t)(k0 + 8) * TGT + n];
        float w11 = W2[(size_t)(k0 + 9) * TGT + n];
        size_t dst = (size_t)2 * (((size_t)kt * 4 + (nt >> 1)) * 32 + lane) + (nt & 1);
        g_w2[dst] = make_uint2(pack2h(w00, w01), pack2h(w10, w11));
    }
}

// ===================== main fused kernel =====================
extern "C" __global__ void __launch_bounds__(THREADS, 1)
edge_mlp(const float* __restrict__ ek, const float* __restrict__ vrk,
         const float* __restrict__ vsk, const float* __restrict__ u,
         const int* __restrict__ batch,
         const float* __restrict__ b1, const float* __restrict__ b2,
         float* __restrict__ out, int ngroups) {
    extern __shared__ __align__(16) unsigned char smem[];
    const int tid = threadIdx.x;

    // -------- prologue: weight fragments + biases to smem --------
    {
        uint4* d = (uint4*)(smem + S_W1);
        const uint4* s = (const uint4*)g_w1;
        for (int i = tid; i < 98304 / 16; i += THREADS) d[i] = s[i];
        d = (uint4*)(smem + S_W2); s = (const uint4*)g_w2;
        for (int i = tid; i < 16384 / 16; i += THREADS) d[i] = s[i];
        float* b1s = (float*)(smem + S_B1);
        float* b2s = (float*)(smem + S_B2);
        if (tid < HID) b1s[tid] = b1[tid];
        if (tid < TGT) b2s[tid] = b2[tid];
    }
    __syncthreads();

    const uint4* w1p = (const uint4*)(smem + S_W1);
    const uint4* w2p = (const uint4*)(smem + S_W2);
    const float* b1s = (const float*)(smem + S_B1);
    const float* b2s = (const float*)(smem + S_B2);

    const int lane = tid & 31;
    const int qrow  = lane >> 2;        // 0..7
    const int qcol  = (lane & 3) * 2;   // 0,2,4,6 (bias / output indexing)
    const int qcol4 = (lane & 3) * 4;   // 0,4,8,12 (coalesced x load, permuted K)

    // dynamic work stealing (group = 16 edge rows)
    unsigned int cur = 0xFFFFFFFFu;
    if (lane == 0) cur = atomicAdd(&g_counter, 1u);
    cur = __shfl_sync(0xFFFFFFFFu, cur, 0);

    while (cur < (unsigned)ngroups) {
        unsigned int nxt = 0xFFFFFFFFu;
        if (lane == 0) nxt = atomicAdd(&g_counter, 1u);   // issued early, latency hidden

        const int r0 = (int)cur * 16 + qrow;
        const int r1 = r0 + 8;
        const int gb0 = batch[r0];
        const int gb1 = batch[r1];

        float acc[64];   // GEMM1 C: 16 n-tiles x 4
        #pragma unroll
        for (int i = 0; i < 64; ++i) acc[i] = 0.f;

        // ================= GEMM1: K = 384 in 24 k16-tiles, pipelined coalesced loads =================
        // Each lane loads ONE float4 per row block: mem cols kt*16 + 4q .. +3 (permuted K).
        float4 v0, v1;
        {
            v0 = *(const float4*)(ek + (size_t)r0 * NEF + qcol4);
            v1 = *(const float4*)(ek + (size_t)r1 * NEF + qcol4);
        }
        #pragma unroll 1
        for (int kt = 0; kt < KT1; ++kt) {
            // ---- prefetch kt+1 (2 fully-coalesced LDG.128) ----
            float4 n0, n1;
            {
                const int kn = (kt + 1 < KT1) ? kt + 1 : KT1 - 1;
                const int c0 = kn * 16 + qcol4;
                const float *p0, *p1;
                if (kn < 4)       { p0 = ek  + (size_t)r0 * NEF + c0;          p1 = ek  + (size_t)r1 * NEF + c0; }
                else if (kn < 12) { p0 = vrk + (size_t)r0 * NNF + (c0 - 64);   p1 = vrk + (size_t)r1 * NNF + (c0 - 64); }
                else if (kn < 20) { p0 = vsk + (size_t)r0 * NNF + (c0 - 192);  p1 = vsk + (size_t)r1 * NNF + (c0 - 192); }
                else              { p0 = u + (size_t)gb0 * NGF + (c0 - 320);   p1 = u + (size_t)gb1 * NGF + (c0 - 320); }
                n0 = *(const float4*)p0;
                n1 = *(const float4*)p1;
            }

            // ---- A fragment (permuted K): .xy -> logical 2q,2q+1 ; .zw -> 2q+8,2q+9 ----
            uint32_t a[4];
            a[0] = pack2h(v0.x, v0.y);   // row r0, logical k 2q,2q+1
            a[1] = pack2h(v1.x, v1.y);   // row r1
            a[2] = pack2h(v0.z, v0.w);   // row r0, logical k 2q+8,2q+9
            a[3] = pack2h(v1.z, v1.w);   // row r1

            const uint4* bw = w1p + (size_t)kt * 8 * 32 + lane;
            #pragma unroll
            for (int np = 0; np < 8; ++np) {
                const uint4 f = bw[np * 32];        // two n-tile fragments per LDS.128
                mma_f16(acc + (np * 2) * 4,     a, f.x, f.y);
                mma_f16(acc + (np * 2 + 1) * 4, a, f.z, f.w);
            }

            v0 = n0; v1 = n1;
        }

        // ================= bias + ReLU =================
        #pragma unroll
        for (int nt = 0; nt < NT1; ++nt) {
            const float2 bb = *(const float2*)(b1s + nt * 8 + qcol);
            acc[nt * 4 + 0] = fmaxf(acc[nt * 4 + 0] + bb.x, 0.f);
            acc[nt * 4 + 1] = fmaxf(acc[nt * 4 + 1] + bb.y, 0.f);
            acc[nt * 4 + 2] = fmaxf(acc[nt * 4 + 2] + bb.x, 0.f);
            acc[nt * 4 + 3] = fmaxf(acc[nt * 4 + 3] + bb.y, 0.f);
        }

        // ================= GEMM2: h [16x128] @ W2 [128x64], register A (standard layout) =================
        float c2[32];
        #pragma unroll
        for (int i = 0; i < 32; ++i) c2[i] = 0.f;

        #pragma unroll
        for (int kt = 0; kt < KT2; ++kt) {
            // C1 fragment (n-tiles 2kt,2kt+1) == A2 fragment for k-cols 16kt..16kt+15
            const float* s0 = acc + kt * 8;
            uint32_t a[4];
            a[0] = pack2h(s0[0], s0[1]); a[1] = pack2h(s0[2], s0[3]);
            a[2] = pack2h(s0[4], s0[5]); a[3] = pack2h(s0[6], s0[7]);

            const uint4* bw = w2p + (size_t)kt * 4 * 32 + lane;
            #pragma unroll
            for (int np = 0; np < 4; ++np) {
                const uint4 f = bw[np * 32];
                mma_f16(c2 + (np * 2) * 4,     a, f.x, f.y);
                mma_f16(c2 + (np * 2 + 1) * 4, a, f.z, f.w);
            }
        }

        // ================= epilogue: + b2, store fp32 =================
        #pragma unroll
        for (int nt = 0; nt < NT2; ++nt) {
            const float2 bb = *(const float2*)(b2s + nt * 8 + qcol);
            float2 o0, o1;
            o0.x = c2[nt * 4 + 0] + bb.x;
            o0.y = c2[nt * 4 + 1] + bb.y;
            o1.x = c2[nt * 4 + 2] + bb.x;
            o1.y = c2[nt * 4 + 3] + bb.y;
            *(float2*)(out + (size_t)r0 * TGT + nt * 8 + qcol) = o0;
            *(float2*)(out + (size_t)r1 * TGT + nt * 8 + qcol) = o1;
        }

        cur = __shfl_sync(0xFFFFFFFFu, nxt, 0);
    }
}

// ===================== launch =====================
extern "C" void kernel_launch(void* const* d_in, const int* in_sizes, int n_in,
                              void* d_out, int out_size) {
    (void)n_in; (void)out_size;
    const float* ek  = (const float*)d_in[0];
    const float* vrk = (const float*)d_in[1];
    const float* vsk = (const float*)d_in[2];
    const float* u   = (const float*)d_in[3];
    const int*   batch = (const int*)d_in[4];
    const float* W1  = (const float*)d_in[5];
    const float* b1  = (const float*)d_in[6];
    const float* W2  = (const float*)d_in[7];
    const float* b2  = (const float*)d_in[8];
    float* out = (float*)d_out;

    const int E = in_sizes[0] / NEF;
    const int ngroups = E / 16;

    const int prep_total = KT1 * NT1 * 32 + KT2 * NT2 * 32;
    prep_kernel<<<(prep_total + 255) / 256, 256>>>(W1, W2);

    cudaFuncSetAttribute(edge_mlp, cudaFuncAttributeMaxDynamicSharedMemorySize, S_TOTAL);
    edge_mlp<<<GRID_X, THREADS, S_TOTAL>>>(ek, vrk, vsk, u, batch, b1, b2, out, ngroups);
}

// round 15
// speedup vs baseline: 2.3786x; 1.1308x over previous
#include <cuda_runtime.h>
#include <cuda_fp16.h>
#include <cstdint>

// ===================== problem constants =====================
#define NNF 128
#define NEF 64
#define NGF 64
#define HID 128
#define TGT 64

#define THREADS 480
#define WARPS 15
#define GRID_X 152

// fragment tile counts
#define KT1 24   // 384/16 k-tiles, GEMM1
#define NT1 16   // 128/8  n-tiles, GEMM1
#define KT2 8    // 128/16 k-tiles, GEMM2
#define NT2 8    // 64/8   n-tiles, GEMM2

// ===================== smem offsets (bytes) =====================
#define S_W1  0u        // 24 kt x 8 pairs x 32 lanes x 16B = 98304
#define S_W2  98304u    // 8 kt x 4 pairs x 32 x 16B = 16384
#define S_B1  114688u   // 512
#define S_B2  115200u   // 256
#define S_TOTAL 115456u

// ===================== helpers =====================
__device__ __forceinline__ uint32_t pack2h(float lo, float hi) {
    // f16x2 with 'lo' in low 16 bits (first PTX source -> high half)
    uint32_t r;
    asm("cvt.rn.f16x2.f32 %0, %1, %2;" : "=r"(r) : "f"(hi), "f"(lo));
    return r;
}
// D += A * B  (m16n8k16, fp16 in, f32 accum)
__device__ __forceinline__ void mma_f16(float* c, const uint32_t* a, uint32_t b0, uint32_t b1) {
    asm volatile("mma.sync.aligned.m16n8k16.row.col.f32.f16.f16.f32 "
        "{%0,%1,%2,%3}, {%4,%5,%6,%7}, {%8,%9}, {%0,%1,%2,%3};"
        : "+f"(c[0]), "+f"(c[1]), "+f"(c[2]), "+f"(c[3])
        : "r"(a[0]), "r"(a[1]), "r"(a[2]), "r"(a[3]), "r"(b0), "r"(b1));
}

// ===================== device scratch (pair-interleaved fragments) =====================
__device__ __align__(16) uint2 g_w1[KT1 * NT1 * 32];
__device__ __align__(16) uint2 g_w2[KT2 * NT2 * 32];
__device__ unsigned int g_counter;

// W1 [384,128] ([k][n] row-major) -> per-lane m16n8k16 B fragments (fp16), with a
// K-PERMUTATION inside each 16-k tile: logical k {2q,2q+1,2q+8,2q+9} <- memory
// cols {4q,4q+1,4q+2,4q+3} (q = lane&3):
//   b0 = {W[k0][n], W[k0+1][n]},  b1 = {W[k0+2][n], W[k0+3][n]},  k0 = kt*16 + 4q.
// The A side loads one contiguous float4 (cols 4q..4q+3); .xy -> a0/a1, .zw -> a2/a3.
// Same permutation on both operands => k-sum invariant.
// W2 [128,64] keeps the STANDARD layout (A comes from registers in logical order):
//   b0 = {W[k0][n], W[k0+1][n]}, b1 = {W[k0+8][n], W[k0+9][n]}, k0 = kt*16 + 2q.
// PAIRED storage: uint4 entry ((kt*NP+np)*32+lane) = {frag(nt=2np), frag(nt=2np+1)}.
__global__ void prep_kernel(const float* __restrict__ W1, const float* __restrict__ W2) {
    int idx = blockIdx.x * blockDim.x + threadIdx.x;
    if (idx == 0) g_counter = 0u;
    const int total1 = KT1 * NT1 * 32;
    if (idx < total1) {
        int lane = idx & 31, tile = idx >> 5;
        int nt = tile % NT1, kt = tile / NT1;
        int k0 = kt * 16 + (lane & 3) * 4;        // permuted: 4 consecutive rows
        int n  = nt * 8 + (lane >> 2);
        float w00 = W1[(size_t)k0 * HID + n];
        float w01 = W1[(size_t)(k0 + 1) * HID + n];
        float w10 = W1[(size_t)(k0 + 2) * HID + n];
        float w11 = W1[(size_t)(k0 + 3) * HID + n];
        size_t dst = (size_t)2 * (((size_t)kt * 8 + (nt >> 1)) * 32 + lane) + (nt & 1);
        g_w1[dst] = make_uint2(pack2h(w00, w01), pack2h(w10, w11));
    } else if (idx < total1 + KT2 * NT2 * 32) {
        int j = idx - total1;
        int lane = j & 31, tile = j >> 5;
        int nt = tile % NT2, kt = tile / NT2;
        int k0 = kt * 16 + (lane & 3) * 2;        // standard layout for W2
        int n  = nt * 8 + (lane >> 2);
        float w00 = W2[(size_t)k0 * TGT + n];
        float w01 = W2[(size_t)(k0 + 1) * TGT + n];
        float w10 = W2[(size_t)(k0 + 8) * TGT + n];
        float w11 = W2[(size_t)(k0 + 9) * TGT + n];
        size_t dst = (size_t)2 * (((size_t)kt * 4 + (nt >> 1)) * 32 + lane) + (nt & 1);
        g_w2[dst] = make_uint2(pack2h(w00, w01), pack2h(w10, w11));
    }
}

// coalesced x load for (permuted) k-tile kn: one float4 per row block
__device__ __forceinline__ void loadx(float4& x0, float4& x1, int kn,
                                      const float* __restrict__ ek, const float* __restrict__ vrk,
                                      const float* __restrict__ vsk, const float* __restrict__ u,
                                      int r0, int r1, int gb0, int gb1, int qcol4) {
    const int c0 = kn * 16 + qcol4;
    const float *p0, *p1;
    if (kn < 4)       { p0 = ek  + (size_t)r0 * NEF + c0;          p1 = ek  + (size_t)r1 * NEF + c0; }
    else if (kn < 12) { p0 = vrk + (size_t)r0 * NNF + (c0 - 64);   p1 = vrk + (size_t)r1 * NNF + (c0 - 64); }
    else if (kn < 20) { p0 = vsk + (size_t)r0 * NNF + (c0 - 192);  p1 = vsk + (size_t)r1 * NNF + (c0 - 192); }
    else              { p0 = u + (size_t)gb0 * NGF + (c0 - 320);   p1 = u + (size_t)gb1 * NGF + (c0 - 320); }
    x0 = *(const float4*)p0;
    x1 = *(const float4*)p1;
}

// ===================== main fused kernel =====================
extern "C" __global__ void __launch_bounds__(THREADS, 1)
edge_mlp(const float* __restrict__ ek, const float* __restrict__ vrk,
         const float* __restrict__ vsk, const float* __restrict__ u,
         const int* __restrict__ batch,
         const float* __restrict__ b1, const float* __restrict__ b2,
         float* __restrict__ out, int ngroups) {
    extern __shared__ __align__(16) unsigned char smem[];
    const int tid = threadIdx.x;

    // -------- prologue: weight fragments + biases to smem --------
    {
        uint4* d = (uint4*)(smem + S_W1);
        const uint4* s = (const uint4*)g_w1;
        for (int i = tid; i < 98304 / 16; i += THREADS) d[i] = s[i];
        d = (uint4*)(smem + S_W2); s = (const uint4*)g_w2;
        for (int i = tid; i < 16384 / 16; i += THREADS) d[i] = s[i];
        float* b1s = (float*)(smem + S_B1);
        float* b2s = (float*)(smem + S_B2);
        if (tid < HID) b1s[tid] = b1[tid];
        if (tid < TGT) b2s[tid] = b2[tid];
    }
    __syncthreads();

    const uint4* w1p = (const uint4*)(smem + S_W1);
    const uint4* w2p = (const uint4*)(smem + S_W2);
    const float* b1s = (const float*)(smem + S_B1);
    const float* b2s = (const float*)(smem + S_B2);

    const int lane = tid & 31;
    const int qrow  = lane >> 2;        // 0..7
    const int qcol  = (lane & 3) * 2;   // 0,2,4,6 (bias / output indexing)
    const int qcol4 = (lane & 3) * 4;   // 0,4,8,12 (coalesced x load, permuted K)

    // dynamic work stealing (group = 16 edge rows)
    unsigned int cur = 0xFFFFFFFFu;
    if (lane == 0) cur = atomicAdd(&g_counter, 1u);
    cur = __shfl_sync(0xFFFFFFFFu, cur, 0);

    while (cur < (unsigned)ngroups) {
        unsigned int nxt = 0xFFFFFFFFu;
        if (lane == 0) nxt = atomicAdd(&g_counter, 1u);   // issued early, latency hidden

        const int r0 = (int)cur * 16 + qrow;
        const int r1 = r0 + 8;
        const int gb0 = batch[r0];
        const int gb1 = batch[r1];

        float acc[64];   // GEMM1 C: 16 n-tiles x 4
        #pragma unroll
        for (int i = 0; i < 64; ++i) acc[i] = 0.f;

        // ================= GEMM1: K = 384, unroll-2 kt loop, distance-2 prefetch =================
        float4 vA0, vA1, vB0, vB1;
        loadx(vA0, vA1, 0, ek, vrk, vsk, u, r0, r1, gb0, gb1, qcol4);   // kt = 0
        loadx(vB0, vB1, 1, ek, vrk, vsk, u, r0, r1, gb0, gb1, qcol4);   // kt = 1

        #pragma unroll 1
        for (int kt = 0; kt < KT1; kt += 2) {
            // ---- even tile kt: consume vA (loaded 2 bodies ago), refill for kt+2 ----
            {
                uint32_t a[4];
                a[0] = pack2h(vA0.x, vA0.y);
                a[1] = pack2h(vA1.x, vA1.y);
                a[2] = pack2h(vA0.z, vA0.w);
                a[3] = pack2h(vA1.z, vA1.w);
                if (kt + 2 < KT1)
                    loadx(vA0, vA1, kt + 2, ek, vrk, vsk, u, r0, r1, gb0, gb1, qcol4);
                const uint4* bw = w1p + (size_t)kt * 8 * 32 + lane;
                #pragma unroll
                for (int np = 0; np < 8; ++np) {
                    const uint4 f = bw[np * 32];
                    mma_f16(acc + (np * 2) * 4,     a, f.x, f.y);
                    mma_f16(acc + (np * 2 + 1) * 4, a, f.z, f.w);
                }
            }
            // ---- odd tile kt+1: consume vB, refill for kt+3 ----
            {
                uint32_t a[4];
                a[0] = pack2h(vB0.x, vB0.y);
                a[1] = pack2h(vB1.x, vB1.y);
                a[2] = pack2h(vB0.z, vB0.w);
                a[3] = pack2h(vB1.z, vB1.w);
                if (kt + 3 < KT1)
                    loadx(vB0, vB1, kt + 3, ek, vrk, vsk, u, r0, r1, gb0, gb1, qcol4);
                const uint4* bw = w1p + (size_t)(kt + 1) * 8 * 32 + lane;
                #pragma unroll
                for (int np = 0; np < 8; ++np) {
                    const uint4 f = bw[np * 32];
                    mma_f16(acc + (np * 2) * 4,     a, f.x, f.y);
                    mma_f16(acc + (np * 2 + 1) * 4, a, f.z, f.w);
                }
            }
        }

        // ================= bias + ReLU =================
        #pragma unroll
        for (int nt = 0; nt < NT1; ++nt) {
            const float2 bb = *(const float2*)(b1s + nt * 8 + qcol);
            acc[nt * 4 + 0] = fmaxf(acc[nt * 4 + 0] + bb.x, 0.f);
            acc[nt * 4 + 1] = fmaxf(acc[nt * 4 + 1] + bb.y, 0.f);
            acc[nt * 4 + 2] = fmaxf(acc[nt * 4 + 2] + bb.x, 0.f);
            acc[nt * 4 + 3] = fmaxf(acc[nt * 4 + 3] + bb.y, 0.f);
        }

        // ================= GEMM2: h [16x128] @ W2 [128x64], register A (standard layout) =================
        float c2[32];
        #pragma unroll
        for (int i = 0; i < 32; ++i) c2[i] = 0.f;

        #pragma unroll
        for (int kt = 0; kt < KT2; ++kt) {
            // C1 fragment (n-tiles 2kt,2kt+1) == A2 fragment for k-cols 16kt..16kt+15
            const float* s0 = acc + kt * 8;
            uint32_t a[4];
            a[0] = pack2h(s0[0], s0[1]); a[1] = pack2h(s0[2], s0[3]);
            a[2] = pack2h(s0[4], s0[5]); a[3] = pack2h(s0[6], s0[7]);

            const uint4* bw = w2p + (size_t)kt * 4 * 32 + lane;
            #pragma unroll
            for (int np = 0; np < 4; ++np) {
                const uint4 f = bw[np * 32];
                mma_f16(c2 + (np * 2) * 4,     a, f.x, f.y);
                mma_f16(c2 + (np * 2 + 1) * 4, a, f.z, f.w);
            }
        }

        // ================= epilogue: + b2, store fp32 =================
        #pragma unroll
        for (int nt = 0; nt < NT2; ++nt) {
            const float2 bb = *(const float2*)(b2s + nt * 8 + qcol);
            float2 o0, o1;
            o0.x = c2[nt * 4 + 0] + bb.x;
            o0.y = c2[nt * 4 + 1] + bb.y;
            o1.x = c2[nt * 4 + 2] + bb.x;
            o1.y = c2[nt * 4 + 3] + bb.y;
            *(float2*)(out + (size_t)r0 * TGT + nt * 8 + qcol) = o0;
            *(float2*)(out + (size_t)r1 * TGT + nt * 8 + qcol) = o1;
        }

        cur = __shfl_sync(0xFFFFFFFFu, nxt, 0);
    }
}

// ===================== launch =====================
extern "C" void kernel_launch(void* const* d_in, const int* in_sizes, int n_in,
                              void* d_out, int out_size) {
    (void)n_in; (void)out_size;
    const float* ek  = (const float*)d_in[0];
    const float* vrk = (const float*)d_in[1];
    const float* vsk = (const float*)d_in[2];
    const float* u   = (const float*)d_in[3];
    const int*   batch = (const int*)d_in[4];
    const float* W1  = (const float*)d_in[5];
    const float* b1  = (const float*)d_in[6];
    const float* W2  = (const float*)d_in[7];
    const float* b2  = (const float*)d_in[8];
    float* out = (float*)d_out;

    const int E = in_sizes[0] / NEF;
    const int ngroups = E / 16;

    const int prep_total = KT1 * NT1 * 32 + KT2 * NT2 * 32;
    prep_kernel<<<(prep_total + 255) / 256, 256>>>(W1, W2);

    cudaFuncSetAttribute(edge_mlp, cudaFuncAttributeMaxDynamicSharedMemorySize, S_TOTAL);
    edge_mlp<<<GRID_X, THREADS, S_TOTAL>>>(ek, vrk, vsk, u, batch, b1, b2, out, ngroups);
}